// round 2
// baseline (speedup 1.0000x reference)
#include <cuda_runtime.h>
#include <stdint.h>

typedef unsigned long long ull;

// ---------- f32x2 packed-fp32 helpers ----------
__device__ __forceinline__ ull pk2(float lo, float hi) {
    ull r; asm("mov.b64 %0,{%1,%2};" : "=l"(r) : "f"(lo), "f"(hi)); return r;
}
__device__ __forceinline__ void upk2(ull v, float& lo, float& hi) {
    asm("mov.b64 {%0,%1},%2;" : "=f"(lo), "=f"(hi) : "l"(v));
}
__device__ __forceinline__ ull ffma2(ull a, ull b, ull c) {
    ull d; asm("fma.rn.f32x2 %0,%1,%2,%3;" : "=l"(d) : "l"(a), "l"(b), "l"(c)); return d;
}

// ---------- DSMEM / mbarrier helpers ----------
__device__ __forceinline__ uint32_t s2u(const void* p) {
    uint32_t a;
    asm("{ .reg .u64 t; cvta.to.shared.u64 t, %1; cvt.u32.u64 %0, t; }" : "=r"(a) : "l"(p));
    return a;
}
__device__ __forceinline__ void st_cluster_b64(uint32_t laddr, uint32_t rank, ull v) {
    asm volatile(
        "{ .reg .b32 ra; mapa.shared::cluster.u32 ra, %0, %1;"
        " st.shared::cluster.b64 [ra], %2; }"
        :: "r"(laddr), "r"(rank), "l"(v) : "memory");
}
__device__ __forceinline__ void mbar_init(uint32_t a, uint32_t cnt) {
    asm volatile("mbarrier.init.shared.b64 [%0], %1;" :: "r"(a), "r"(cnt) : "memory");
}
__device__ __forceinline__ void arrive_cluster(uint32_t laddr, uint32_t rank) {
    asm volatile(
        "{ .reg .b32 ra; mapa.shared::cluster.u32 ra, %0, %1;"
        " mbarrier.arrive.release.cluster.shared::cluster.b64 _, [ra]; }"
        :: "r"(laddr), "r"(rank) : "memory");
}
__device__ __forceinline__ void wait_parity_acq_cluster(uint32_t a, uint32_t ph) {
    asm volatile(
        "{ .reg .pred P;\n"
        "WLOOP%=:\n"
        " mbarrier.try_wait.parity.acquire.cluster.shared::cta.b64 P, [%0], %1, 0x989680;\n"
        " @P bra WDONE%=;\n"
        " bra WLOOP%=;\n"
        "WDONE%=:\n"
        "}"
        :: "r"(a), "r"(ph) : "memory");
}

// ---------- problem constants ----------
#define BATCH   64
#define SEQ     2048
#define FEAT    256
#define HID     256
#define G4      1024           // 4*HID
#define BG      4              // batches per cluster
#define CLU     8              // CTAs per cluster (each owns 128 gate cols)

// ---------- scratch (no cudaMalloc allowed) ----------
__device__ float xp_buf[(size_t)BATCH * SEQ * G4];      // x @ Wx + bx + bh

// ============================================================
// x_proj GEMM: xp[bt, g] = sum_f x[bt,f]*Wx[f,g] + Bx[g] + Bh[g]
// ============================================================
__global__ __launch_bounds__(256) void xproj_kernel(
    const float* __restrict__ x, const float* __restrict__ WX,
    const float* __restrict__ BX, const float* __restrict__ BH)
{
    __shared__ float xs[64][68];   // [k][row], padded
    __shared__ float ws[64][64];   // [k][col]

    const int tid = threadIdx.x;
    const int ty = tid >> 4, tx = tid & 15;
    const size_t row0 = (size_t)blockIdx.x * 64;
    const int col0 = blockIdx.y * 64;

    ull acc[4][2];
#pragma unroll
    for (int i = 0; i < 4; i++) { acc[i][0] = pk2(0.f, 0.f); acc[i][1] = pk2(0.f, 0.f); }

    for (int kc = 0; kc < FEAT; kc += 64) {
#pragma unroll
        for (int i = 0; i < 4; i++) {
            int rr = (tid >> 4) + 16 * i;
            float4 v = *(const float4*)&x[(row0 + rr) * FEAT + kc + (tid & 15) * 4];
            int kb = (tid & 15) * 4;
            xs[kb + 0][rr] = v.x; xs[kb + 1][rr] = v.y;
            xs[kb + 2][rr] = v.z; xs[kb + 3][rr] = v.w;
        }
#pragma unroll
        for (int i = 0; i < 4; i++) {
            int kk = (tid >> 4) + 16 * i;
            float4 v = *(const float4*)&WX[(size_t)(kc + kk) * G4 + col0 + (tid & 15) * 4];
            *(float4*)&ws[kk][(tid & 15) * 4] = v;
        }
        __syncthreads();
#pragma unroll 16
        for (int kk = 0; kk < 64; kk++) {
            float4 a4 = *(const float4*)&xs[kk][4 * ty];
            float4 b4 = *(const float4*)&ws[kk][4 * tx];
            ull b01 = pk2(b4.x, b4.y), b23 = pk2(b4.z, b4.w);
            ull am;
            am = pk2(a4.x, a4.x); acc[0][0] = ffma2(am, b01, acc[0][0]); acc[0][1] = ffma2(am, b23, acc[0][1]);
            am = pk2(a4.y, a4.y); acc[1][0] = ffma2(am, b01, acc[1][0]); acc[1][1] = ffma2(am, b23, acc[1][1]);
            am = pk2(a4.z, a4.z); acc[2][0] = ffma2(am, b01, acc[2][0]); acc[2][1] = ffma2(am, b23, acc[2][1]);
            am = pk2(a4.w, a4.w); acc[3][0] = ffma2(am, b01, acc[3][0]); acc[3][1] = ffma2(am, b23, acc[3][1]);
        }
        __syncthreads();
    }

    const int gc = col0 + 4 * tx;
    float4 bx4 = *(const float4*)&BX[gc];
    float4 bh4 = *(const float4*)&BH[gc];
    float4 bias = make_float4(bx4.x + bh4.x, bx4.y + bh4.y, bx4.z + bh4.z, bx4.w + bh4.w);
#pragma unroll
    for (int i = 0; i < 4; i++) {
        float4 o;
        upk2(acc[i][0], o.x, o.y);
        upk2(acc[i][1], o.z, o.w);
        o.x += bias.x; o.y += bias.y; o.z += bias.z; o.w += bias.w;
        *(float4*)&xp_buf[(row0 + 4 * ty + i) * G4 + gc] = o;
    }
}

// ============================================================
// LSTM recurrence: 16 clusters x 8 CTAs. Cluster g handles
// batches [4g, 4g+4). CTA rank r holds WeightH cols
// {gate*256 + 32r + jj} in REGISTERS (128 regs/thread, f32x2-packed).
// h exchanged via DSMEM (pre-duplicated (h,h) pairs, double-buffered)
// with an mbarrier (8 arrivals) per CTA per step.
// ============================================================
__device__ __forceinline__ float fsig(float x) {
    return __fdividef(1.0f, 1.0f + __expf(-x));
}
__device__ __forceinline__ float ftanh(float x) { return 2.0f * fsig(2.0f * x) - 1.0f; }

__global__ __launch_bounds__(256, 1) __cluster_dims__(CLU, 1, 1)
void lstm_kernel(float* __restrict__ out, const float* __restrict__ WH, long long out_size)
{
    __shared__ ull    hd[2][HID][BG];     // (h,h) dup per [phase][k][b]   16 KB
    __shared__ float4 red[BG][256];       // partials [b][ks*32+cq]        16 KB
    __shared__ float  gates[BG][128];     //                                2 KB
    __shared__ ull    mbar;

    const int tid = threadIdx.x;
    uint32_t rnk; asm("mov.u32 %0, %%cluster_ctarank;" : "=r"(rnk));
    const int r = (int)rnk;
    const int grp = blockIdx.x >> 3;
    const int batch0 = grp * BG;

    const int ks = tid >> 5;            // GEMM: K-split 0..7 (warp id)
    const int cq = tid & 31;            // GEMM: col-quad (local cols 4cq..4cq+3)
    const int rb = tid >> 5;            // reducer/activation batch (tid<128 -> 0..3)
    const int rc = tid & 31;            // reducer col-quad / activation hidden unit

    const uint32_t mbar_a = s2u(&mbar);
    const uint32_t hslot_a[1] = { 0 };  (void)hslot_a;

    // ---- init: mbar (8 arrivals/phase), zero h phase-0 buffer ----
    if (tid == 0) mbar_init(mbar_a, CLU);
    for (int i = tid; i < HID * BG; i += 256) hd[0][i >> 2][i & 3] = 0ull;
    __syncthreads();
    asm volatile("barrier.cluster.arrive.aligned;" ::: "memory");

    // ---- load WeightH slice into registers (packed f32x2 col pairs) ----
    ull wA[32], wB[32];
    {
        const int gc = (cq >> 3) * HID + 32 * r + ((4 * cq) & 31);
        const float* wp = WH + (size_t)(32 * ks) * G4 + gc;
#pragma unroll
        for (int kk = 0; kk < 32; kk++) {
            float4 w4 = *(const float4*)(wp + (size_t)kk * G4);
            wA[kk] = pk2(w4.x, w4.y);
            wB[kk] = pk2(w4.z, w4.w);
        }
    }

    // ---- prefetch x_proj for t=0 ----
    float4 xp4 = make_float4(0.f, 0.f, 0.f, 0.f);
    size_t xbase = 0;
    if (tid < 128) {
        xbase = ((size_t)(batch0 + rb) * SEQ) * G4 + (rc >> 3) * HID + 32 * r + ((4 * rc) & 31);
        xp4 = *(const float4*)&xp_buf[xbase];
    }

    asm volatile("barrier.cluster.wait.aligned;" ::: "memory");

    float cstate = 0.0f, hlast = 0.0f;
    int p = 0;
    uint32_t ph = 0;

    for (int t = 0; t < SEQ; t++) {
        // ---- sub-GEMM: (4 batch) x (4 cols) over k in [32ks, 32ks+32) ----
        ull a00, a01, a10, a11, a20, a21, a30, a31;
        a00 = a01 = a10 = a11 = a20 = a21 = a30 = a31 = pk2(0.f, 0.f);
        {
            const ull* hp = &hd[p][ks * 32][0];
#pragma unroll
            for (int kk = 0; kk < 32; kk++) {
                ulonglong2 d0 = *(const ulonglong2*)(hp + kk * 4);
                ulonglong2 d1 = *(const ulonglong2*)(hp + kk * 4 + 2);
                a00 = ffma2(d0.x, wA[kk], a00); a01 = ffma2(d0.x, wB[kk], a01);
                a10 = ffma2(d0.y, wA[kk], a10); a11 = ffma2(d0.y, wB[kk], a11);
                a20 = ffma2(d1.x, wA[kk], a20); a21 = ffma2(d1.x, wB[kk], a21);
                a30 = ffma2(d1.y, wA[kk], a30); a31 = ffma2(d1.y, wB[kk], a31);
            }
        }
        {   // stage partials: red[b][tid] — coalesced, conflict-free
            float4 v;
            upk2(a00, v.x, v.y); upk2(a01, v.z, v.w); red[0][tid] = v;
            upk2(a10, v.x, v.y); upk2(a11, v.z, v.w); red[1][tid] = v;
            upk2(a20, v.x, v.y); upk2(a21, v.z, v.w); red[2][tid] = v;
            upk2(a30, v.x, v.y); upk2(a31, v.z, v.w); red[3][tid] = v;
        }
        __syncthreads();

        // ---- reduce 8 K-splits + x_proj -> gates (warp-uniform batch) ----
        if (tid < 128) {
            float4 s = xp4;
#pragma unroll
            for (int j = 0; j < 8; j++) {
                float4 v = red[rb][j * 32 + rc];
                s.x += v.x; s.y += v.y; s.z += v.z; s.w += v.w;
            }
            *(float4*)&gates[rb][4 * rc] = s;
        }
        __syncthreads();

        // ---- activations + state update + h broadcast (DSMEM) ----
        if (tid < 128) {
            float gi = gates[rb][      rc];
            float gf = gates[rb][ 32 + rc];
            float gg = gates[rb][ 64 + rc];
            float go = gates[rb][ 96 + rc];
            float i_ = fsig(gi), f_ = fsig(gf), g_ = ftanh(gg), o_ = fsig(go);
            cstate = f_ * cstate + i_ * g_;
            float h_ = o_ * ftanh(cstate);
            hlast = h_;
            const int kidx = 32 * r + rc;
            // write (h,h) dup into all 8 cluster CTAs' next-phase buffer
            ull hv = pk2(h_, h_);
            uint32_t dst = s2u(&hd[p ^ 1][kidx][rb]);
#pragma unroll
            for (int q = 0; q < CLU; q++) st_cluster_b64(dst, q, hv);
            out[((size_t)(batch0 + rb) * SEQ + t) * HID + kidx] = h_;
        }
        __syncthreads();

        // ---- publish: one release-arrive per peer CTA ----
        if (tid == 0) {
#pragma unroll
            for (int q = 0; q < CLU; q++) arrive_cluster(mbar_a, q);
        }

        // ---- prefetch next step's x_proj while waiting ----
        if (tid < 128) {
            int tn = (t + 1 < SEQ) ? (t + 1) : t;
            xp4 = *(const float4*)&xp_buf[xbase + (size_t)tn * G4];
        }

        wait_parity_acq_cluster(mbar_a, ph);
        ph ^= 1u;
        p ^= 1;
    }

    // ---- h_n (second output region) ----
    if (tid < 128 && out_size >= (long long)BATCH * SEQ * HID + BATCH * HID) {
        out[(size_t)BATCH * SEQ * HID + (size_t)(batch0 + rb) * HID + 32 * r + rc] = hlast;
    }
}

// ============================================================
extern "C" void kernel_launch(void* const* d_in, const int* in_sizes, int n_in,
                              void* d_out, int out_size)
{
    const float* x  = (const float*)d_in[0];
    const float* WX = (const float*)d_in[1];
    const float* WH = (const float*)d_in[2];
    const float* BX = (const float*)d_in[3];
    const float* BH = (const float*)d_in[4];
    float* out = (float*)d_out;

    dim3 gx((BATCH * SEQ) / 64, G4 / 64);
    xproj_kernel<<<gx, 256>>>(x, WX, BX, BH);

    lstm_kernel<<<16 * CLU, 256>>>(out, WH, (long long)out_size);
}

// round 3
// speedup vs baseline: 2.3163x; 2.3163x over previous
#include <cuda_runtime.h>
#include <stdint.h>

typedef unsigned long long ull;

// ---------- f32x2 packed-fp32 helpers ----------
__device__ __forceinline__ ull pk2(float lo, float hi) {
    ull r; asm("mov.b64 %0,{%1,%2};" : "=l"(r) : "f"(lo), "f"(hi)); return r;
}
__device__ __forceinline__ void upk2(ull v, float& lo, float& hi) {
    asm("mov.b64 {%0,%1},%2;" : "=f"(lo), "=f"(hi) : "l"(v));
}
__device__ __forceinline__ ull ffma2(ull a, ull b, ull c) {
    ull d; asm("fma.rn.f32x2 %0,%1,%2,%3;" : "=l"(d) : "l"(a), "l"(b), "l"(c)); return d;
}

// ---------- L2 barrier helpers ----------
__device__ __forceinline__ unsigned ld_acq_gpu(const unsigned* p) {
    unsigned v;
    asm volatile("ld.acquire.gpu.global.u32 %0, [%1];" : "=r"(v) : "l"(p) : "memory");
    return v;
}
__device__ __forceinline__ void red_release_add(unsigned* p, unsigned v) {
    asm volatile("red.release.gpu.global.add.u32 [%0], %1;" :: "l"(p), "r"(v) : "memory");
}

// ---------- problem constants ----------
#define BATCH   64
#define SEQ     2048
#define FEAT    256
#define HID     256
#define G4      1024           // 4*HID
#define BG      4              // batches per group
#define NCTA_PG 8              // CTAs per group
#define NGROUP  16

// ---------- scratch (no cudaMalloc allowed) ----------
__device__ float    xp_buf[(size_t)BATCH * SEQ * G4];       // x @ Wx + bx + bh
__device__ float    h_buf[NGROUP * 2 * HID * BG];           // double-buffered h [grp][p][k][b]
__device__ unsigned bar_arr[NGROUP * 32];                   // 128B-stride counters

// ============================================================
__global__ void init_kernel() {
    int t = blockIdx.x * blockDim.x + threadIdx.x;
    if (t < NGROUP * 2 * HID * BG) h_buf[t] = 0.0f;
    if (t < NGROUP * 32) bar_arr[t] = 0u;
}

// ============================================================
// x_proj GEMM: xp[bt, g] = sum_f x[bt,f]*Wx[f,g] + Bx[g] + Bh[g]
// ============================================================
__global__ __launch_bounds__(256) void xproj_kernel(
    const float* __restrict__ x, const float* __restrict__ WX,
    const float* __restrict__ BX, const float* __restrict__ BH)
{
    __shared__ float xs[64][68];
    __shared__ float ws[64][64];

    const int tid = threadIdx.x;
    const int ty = tid >> 4, tx = tid & 15;
    const size_t row0 = (size_t)blockIdx.x * 64;
    const int col0 = blockIdx.y * 64;

    ull acc[4][2];
#pragma unroll
    for (int i = 0; i < 4; i++) { acc[i][0] = pk2(0.f, 0.f); acc[i][1] = pk2(0.f, 0.f); }

    for (int kc = 0; kc < FEAT; kc += 64) {
#pragma unroll
        for (int i = 0; i < 4; i++) {
            int rr = (tid >> 4) + 16 * i;
            float4 v = *(const float4*)&x[(row0 + rr) * FEAT + kc + (tid & 15) * 4];
            int kb = (tid & 15) * 4;
            xs[kb + 0][rr] = v.x; xs[kb + 1][rr] = v.y;
            xs[kb + 2][rr] = v.z; xs[kb + 3][rr] = v.w;
        }
#pragma unroll
        for (int i = 0; i < 4; i++) {
            int kk = (tid >> 4) + 16 * i;
            float4 v = *(const float4*)&WX[(size_t)(kc + kk) * G4 + col0 + (tid & 15) * 4];
            *(float4*)&ws[kk][(tid & 15) * 4] = v;
        }
        __syncthreads();
#pragma unroll 16
        for (int kk = 0; kk < 64; kk++) {
            float4 a4 = *(const float4*)&xs[kk][4 * ty];
            float4 b4 = *(const float4*)&ws[kk][4 * tx];
            ull b01 = pk2(b4.x, b4.y), b23 = pk2(b4.z, b4.w);
            ull am;
            am = pk2(a4.x, a4.x); acc[0][0] = ffma2(am, b01, acc[0][0]); acc[0][1] = ffma2(am, b23, acc[0][1]);
            am = pk2(a4.y, a4.y); acc[1][0] = ffma2(am, b01, acc[1][0]); acc[1][1] = ffma2(am, b23, acc[1][1]);
            am = pk2(a4.z, a4.z); acc[2][0] = ffma2(am, b01, acc[2][0]); acc[2][1] = ffma2(am, b23, acc[2][1]);
            am = pk2(a4.w, a4.w); acc[3][0] = ffma2(am, b01, acc[3][0]); acc[3][1] = ffma2(am, b23, acc[3][1]);
        }
        __syncthreads();
    }

    const int gc = col0 + 4 * tx;
    float4 bx4 = *(const float4*)&BX[gc];
    float4 bh4 = *(const float4*)&BH[gc];
    float4 bias = make_float4(bx4.x + bh4.x, bx4.y + bh4.y, bx4.z + bh4.z, bx4.w + bh4.w);
#pragma unroll
    for (int i = 0; i < 4; i++) {
        float4 o;
        upk2(acc[i][0], o.x, o.y);
        upk2(acc[i][1], o.z, o.w);
        o.x += bias.x; o.y += bias.y; o.z += bias.z; o.w += bias.w;
        *(float4*)&xp_buf[(row0 + 4 * ty + i) * G4 + gc] = o;
    }
}

// ============================================================
// LSTM recurrence: 16 groups x 8 CTAs (no clusters).
// CTA r in group holds WeightH cols {gate*256+32r+j} in REGISTERS.
// Per step: wait L2 counter -> gather h (ldcg) -> dup to SMEM ->
// f32x2 sub-GEMM -> SMEM reduce -> gates -> c/h update ->
// h to L2 (double-buffered) -> red.release arrive.
// ============================================================
__device__ __forceinline__ float fsig(float x) {
    return __fdividef(1.0f, 1.0f + __expf(-x));
}
__device__ __forceinline__ float ftanh(float x) { return 2.0f * fsig(2.0f * x) - 1.0f; }

__global__ __launch_bounds__(256, 1)
void lstm_kernel(float* __restrict__ out, const float* __restrict__ WH, long long out_size)
{
    __shared__ ull    hd[HID][BG];        // (h,h) dup per [k][b]   8 KB
    __shared__ float4 red_s[BG][256];     // partials [b][ks*32+cq] 16 KB
    __shared__ float  gates_s[BG][128];   //                        2 KB

    const int tid = threadIdx.x;
    const int grp = blockIdx.x >> 3;
    const int r   = blockIdx.x & 7;
    const int batch0 = grp * BG;

    const int ks = tid >> 5;            // GEMM: K-split 0..7 (warp id)
    const int cq = tid & 31;            // GEMM: col-quad (local cols 4cq..4cq+3)
    const int rb = tid >> 5;            // reducer/act batch (tid<128 -> 0..3)
    const int rc = tid & 31;            // reducer col-quad / act hidden unit

    // ---- load WeightH slice into registers (f32x2-packed col pairs) ----
    ull wA[32], wB[32];
    {
        const int gc = (cq >> 3) * HID + 32 * r + ((4 * cq) & 31);
        const float* wp = WH + (size_t)(32 * ks) * G4 + gc;
#pragma unroll
        for (int kk = 0; kk < 32; kk++) {
            float4 w4 = *(const float4*)(wp + (size_t)kk * G4);
            wA[kk] = pk2(w4.x, w4.y);
            wB[kk] = pk2(w4.z, w4.w);
        }
    }

    // ---- prefetch x_proj for t=0 ----
    float4 xp4 = make_float4(0.f, 0.f, 0.f, 0.f);
    size_t xbase = 0;
    if (tid < 128) {
        xbase = ((size_t)(batch0 + rb) * SEQ) * G4 + (rc >> 3) * HID + 32 * r + ((4 * rc) & 31);
        xp4 = *(const float4*)&xp_buf[xbase];
    }

    unsigned* barp = &bar_arr[grp * 32];
    const float4* hb4 = (const float4*)&h_buf[(size_t)grp * 2 * HID * BG];

    float cstate = 0.0f, hlast = 0.0f;
    int p = 0;

    for (int t = 0; t < SEQ; t++) {
        // ---- wait: counter >= 8t (warp 0 polls, broadcast) ----
        if (tid < 32) {
            unsigned target = (unsigned)t << 3;
            while (ld_acq_gpu(barp) < target) { }
        }
        __syncthreads();

        // ---- gather h(t) from L2, dup-pack into SMEM ----
        {
            float4 hv = __ldcg(&hb4[p * 256 + tid]);
            ulonglong2 d0 = make_ulonglong2(pk2(hv.x, hv.x), pk2(hv.y, hv.y));
            ulonglong2 d1 = make_ulonglong2(pk2(hv.z, hv.z), pk2(hv.w, hv.w));
            *(ulonglong2*)&hd[tid][0] = d0;
            *(ulonglong2*)&hd[tid][2] = d1;
        }
        __syncthreads();

        // ---- sub-GEMM: (4 batch) x (4 cols) over k in [32ks, 32ks+32) ----
        ull a00, a01, a10, a11, a20, a21, a30, a31;
        a00 = a01 = a10 = a11 = a20 = a21 = a30 = a31 = pk2(0.f, 0.f);
        {
            const ull* hp = &hd[ks * 32][0];
#pragma unroll
            for (int kk = 0; kk < 32; kk++) {
                ulonglong2 d0 = *(const ulonglong2*)(hp + kk * 4);
                ulonglong2 d1 = *(const ulonglong2*)(hp + kk * 4 + 2);
                a00 = ffma2(d0.x, wA[kk], a00); a01 = ffma2(d0.x, wB[kk], a01);
                a10 = ffma2(d0.y, wA[kk], a10); a11 = ffma2(d0.y, wB[kk], a11);
                a20 = ffma2(d1.x, wA[kk], a20); a21 = ffma2(d1.x, wB[kk], a21);
                a30 = ffma2(d1.y, wA[kk], a30); a31 = ffma2(d1.y, wB[kk], a31);
            }
        }
        {   // stage partials: red_s[b][tid] — coalesced, conflict-free
            float4 v;
            upk2(a00, v.x, v.y); upk2(a01, v.z, v.w); red_s[0][tid] = v;
            upk2(a10, v.x, v.y); upk2(a11, v.z, v.w); red_s[1][tid] = v;
            upk2(a20, v.x, v.y); upk2(a21, v.z, v.w); red_s[2][tid] = v;
            upk2(a30, v.x, v.y); upk2(a31, v.z, v.w); red_s[3][tid] = v;
        }
        __syncthreads();

        // ---- reduce 8 K-splits + x_proj -> gates ----
        if (tid < 128) {
            float4 s = xp4;
#pragma unroll
            for (int j = 0; j < 8; j++) {
                float4 v = red_s[rb][j * 32 + rc];
                s.x += v.x; s.y += v.y; s.z += v.z; s.w += v.w;
            }
            *(float4*)&gates_s[rb][4 * rc] = s;
        }
        __syncthreads();

        // ---- activations + state update + h publish ----
        if (tid < 128) {
            float gi = gates_s[rb][      rc];
            float gf = gates_s[rb][ 32 + rc];
            float gg = gates_s[rb][ 64 + rc];
            float go = gates_s[rb][ 96 + rc];
            float i_ = fsig(gi), f_ = fsig(gf), g_ = ftanh(gg), o_ = fsig(go);
            cstate = f_ * cstate + i_ * g_;
            float h_ = o_ * ftanh(cstate);
            hlast = h_;
            const int kidx = 32 * r + rc;
            h_buf[((size_t)grp * 2 + (p ^ 1)) * HID * BG + kidx * BG + rb] = h_;
            out[((size_t)(batch0 + rb) * SEQ + t) * HID + kidx] = h_;
        }
        __syncthreads();

        // ---- arrive (release) + prefetch next xp while others spin ----
        if (tid == 0) red_release_add(barp, 1u);
        if (tid < 128) {
            int tn = (t + 1 < SEQ) ? (t + 1) : t;
            xp4 = *(const float4*)&xp_buf[xbase + (size_t)tn * G4];
        }
        p ^= 1;
    }

    // ---- h_n (second output region) ----
    if (tid < 128 && out_size >= (long long)BATCH * SEQ * HID + BATCH * HID) {
        out[(size_t)BATCH * SEQ * HID + (size_t)(batch0 + rb) * HID + 32 * r + rc] = hlast;
    }
}

// ============================================================
extern "C" void kernel_launch(void* const* d_in, const int* in_sizes, int n_in,
                              void* d_out, int out_size)
{
    const float* x  = (const float*)d_in[0];
    const float* WX = (const float*)d_in[1];
    const float* WH = (const float*)d_in[2];
    const float* BX = (const float*)d_in[3];
    const float* BH = (const float*)d_in[4];
    float* out = (float*)d_out;

    init_kernel<<<128, 256>>>();

    dim3 gx((BATCH * SEQ) / 64, G4 / 64);
    xproj_kernel<<<gx, 256>>>(x, WX, BX, BH);

    lstm_kernel<<<NGROUP * NCTA_PG, 256>>>(out, WH, (long long)out_size);
}

// round 4
// speedup vs baseline: 2.7184x; 1.1736x over previous
#include <cuda_runtime.h>
#include <stdint.h>

typedef unsigned long long ull;

// ---------- f32x2 packed-fp32 helpers ----------
__device__ __forceinline__ ull pk2(float lo, float hi) {
    ull r; asm("mov.b64 %0,{%1,%2};" : "=l"(r) : "f"(lo), "f"(hi)); return r;
}
__device__ __forceinline__ void upk2(ull v, float& lo, float& hi) {
    asm("mov.b64 {%0,%1},%2;" : "=f"(lo), "=f"(hi) : "l"(v));
}
__device__ __forceinline__ ull ffma2(ull a, ull b, ull c) {
    ull d; asm("fma.rn.f32x2 %0,%1,%2,%3;" : "=l"(d) : "l"(a), "l"(b), "l"(c)); return d;
}

// ---------- relaxed 64-bit L2 atoms (tag+data in one word) ----------
__device__ __forceinline__ ull ld_rlx(const ull* p) {
    ull v;
    asm volatile("ld.relaxed.gpu.global.u64 %0, [%1];" : "=l"(v) : "l"(p) : "memory");
    return v;
}
__device__ __forceinline__ void st_rlx(ull* p, ull v) {
    asm volatile("st.relaxed.gpu.global.u64 [%0], %1;" :: "l"(p), "l"(v) : "memory");
}

// ---------- problem constants ----------
#define BATCH   64
#define SEQ     2048
#define FEAT    256
#define HID     256
#define G4      1024           // 4*HID
#define BG      4              // batches per group
#define NCTA_PG 8              // CTAs per group
#define NGROUP  16

// ---------- scratch (no cudaMalloc allowed) ----------
__device__ float xp_buf[(size_t)BATCH * SEQ * G4];          // x @ Wx + bx + bh
__device__ ull   ht_buf[NGROUP * 2 * HID * BG];             // tagged h: lo=h bits, hi=step tag

// ============================================================
// init: slot parity 0 <- tag 0 / h = 0 (t=0 reads this).
// slot parity 1 keeps stale odd tags (>=2047 or 0) != 1 -> safe.
// ============================================================
__global__ void init_kernel() {
    int t = blockIdx.x * blockDim.x + threadIdx.x;
    if (t < NGROUP * HID * BG) {
        int grp = t / (HID * BG);
        int rem = t % (HID * BG);
        ht_buf[(size_t)grp * 2 * HID * BG + rem] = 0ull;
    }
}

// ============================================================
// x_proj GEMM: xp[bt, g] = sum_f x[bt,f]*Wx[f,g] + Bx[g] + Bh[g]
// ============================================================
__global__ __launch_bounds__(256) void xproj_kernel(
    const float* __restrict__ x, const float* __restrict__ WX,
    const float* __restrict__ BX, const float* __restrict__ BH)
{
    __shared__ float xs[64][68];
    __shared__ float ws[64][64];

    const int tid = threadIdx.x;
    const int ty = tid >> 4, tx = tid & 15;
    const size_t row0 = (size_t)blockIdx.x * 64;
    const int col0 = blockIdx.y * 64;

    ull acc[4][2];
#pragma unroll
    for (int i = 0; i < 4; i++) { acc[i][0] = pk2(0.f, 0.f); acc[i][1] = pk2(0.f, 0.f); }

    for (int kc = 0; kc < FEAT; kc += 64) {
#pragma unroll
        for (int i = 0; i < 4; i++) {
            int rr = (tid >> 4) + 16 * i;
            float4 v = *(const float4*)&x[(row0 + rr) * FEAT + kc + (tid & 15) * 4];
            int kb = (tid & 15) * 4;
            xs[kb + 0][rr] = v.x; xs[kb + 1][rr] = v.y;
            xs[kb + 2][rr] = v.z; xs[kb + 3][rr] = v.w;
        }
#pragma unroll
        for (int i = 0; i < 4; i++) {
            int kk = (tid >> 4) + 16 * i;
            float4 v = *(const float4*)&WX[(size_t)(kc + kk) * G4 + col0 + (tid & 15) * 4];
            *(float4*)&ws[kk][(tid & 15) * 4] = v;
        }
        __syncthreads();
#pragma unroll 16
        for (int kk = 0; kk < 64; kk++) {
            float4 a4 = *(const float4*)&xs[kk][4 * ty];
            float4 b4 = *(const float4*)&ws[kk][4 * tx];
            ull b01 = pk2(b4.x, b4.y), b23 = pk2(b4.z, b4.w);
            ull am;
            am = pk2(a4.x, a4.x); acc[0][0] = ffma2(am, b01, acc[0][0]); acc[0][1] = ffma2(am, b23, acc[0][1]);
            am = pk2(a4.y, a4.y); acc[1][0] = ffma2(am, b01, acc[1][0]); acc[1][1] = ffma2(am, b23, acc[1][1]);
            am = pk2(a4.z, a4.z); acc[2][0] = ffma2(am, b01, acc[2][0]); acc[2][1] = ffma2(am, b23, acc[2][1]);
            am = pk2(a4.w, a4.w); acc[3][0] = ffma2(am, b01, acc[3][0]); acc[3][1] = ffma2(am, b23, acc[3][1]);
        }
        __syncthreads();
    }

    const int gc = col0 + 4 * tx;
    float4 bx4 = *(const float4*)&BX[gc];
    float4 bh4 = *(const float4*)&BH[gc];
    float4 bias = make_float4(bx4.x + bh4.x, bx4.y + bh4.y, bx4.z + bh4.z, bx4.w + bh4.w);
#pragma unroll
    for (int i = 0; i < 4; i++) {
        float4 o;
        upk2(acc[i][0], o.x, o.y);
        upk2(acc[i][1], o.z, o.w);
        o.x += bias.x; o.y += bias.y; o.z += bias.z; o.w += bias.w;
        *(float4*)&xp_buf[(row0 + 4 * ty + i) * G4 + gc] = o;
    }
}

// ============================================================
// LSTM recurrence: 16 groups x 8 CTAs. CTA r holds WeightH cols
// {gate*256+32r+j} in REGISTERS. Sync = tagged h words in L2:
// publish h as (tag<<32)|bits, consumers spin on the tag and the
// detecting load already carries the data. No barrier, no atomic.
// ============================================================
__device__ __forceinline__ float fsig(float x) {
    return __fdividef(1.0f, 1.0f + __expf(-x));
}
__device__ __forceinline__ float ftanh(float x) { return 2.0f * fsig(2.0f * x) - 1.0f; }

__global__ __launch_bounds__(256, 1)
void lstm_kernel(float* __restrict__ out, const float* __restrict__ WH, long long out_size)
{
    __shared__ ull    hd[HID][BG];        // (h,h) dup per [k][b]   8 KB
    __shared__ float4 red_s[BG][256];     // partials [b][ks*32+cq] 16 KB
    __shared__ float  gates_s[BG][128];   //                        2 KB

    const int tid = threadIdx.x;
    const int grp = blockIdx.x >> 3;
    const int r   = blockIdx.x & 7;
    const int batch0 = grp * BG;

    const int ks = tid >> 5;            // GEMM: K-split 0..7 (warp id)
    const int cq = tid & 31;            // GEMM: col-quad (local cols 4cq..4cq+3)
    const int rb = tid >> 5;            // reducer/act batch (tid<128 -> 0..3)
    const int rc = tid & 31;            // reducer col-quad / act hidden unit

    // ---- load WeightH slice into registers (f32x2-packed col pairs) ----
    ull wA[32], wB[32];
    {
        const int gc = (cq >> 3) * HID + 32 * r + ((4 * cq) & 31);
        const float* wp = WH + (size_t)(32 * ks) * G4 + gc;
#pragma unroll
        for (int kk = 0; kk < 32; kk++) {
            float4 w4 = *(const float4*)(wp + (size_t)kk * G4);
            wA[kk] = pk2(w4.x, w4.y);
            wB[kk] = pk2(w4.z, w4.w);
        }
    }

    // ---- prefetch x_proj for t=0 ----
    float4 xp4 = make_float4(0.f, 0.f, 0.f, 0.f);
    size_t xbase = 0;
    if (tid < 128) {
        xbase = ((size_t)(batch0 + rb) * SEQ) * G4 + (rc >> 3) * HID + 32 * r + ((4 * rc) & 31);
        xp4 = *(const float4*)&xp_buf[xbase];
    }

    ull* ht = &ht_buf[(size_t)grp * 2 * HID * BG];   // [parity][k][b]

    float cstate = 0.0f, hlast = 0.0f;

    for (int t = 0; t < SEQ; t++) {
        // ---- poll tagged h(t-1): thread tid owns k=tid, 4 batches ----
        {
            ull* sp = ht + ((size_t)(t & 1) * HID + tid) * BG;
            const unsigned tg = (unsigned)t;
            ull v0 = ld_rlx(sp + 0), v1 = ld_rlx(sp + 1);
            ull v2 = ld_rlx(sp + 2), v3 = ld_rlx(sp + 3);
            while (((unsigned)(v0 >> 32) != tg) | ((unsigned)(v1 >> 32) != tg) |
                   ((unsigned)(v2 >> 32) != tg) | ((unsigned)(v3 >> 32) != tg)) {
                v0 = ld_rlx(sp + 0); v1 = ld_rlx(sp + 1);
                v2 = ld_rlx(sp + 2); v3 = ld_rlx(sp + 3);
            }
            float h0 = __uint_as_float((unsigned)v0);
            float h1 = __uint_as_float((unsigned)v1);
            float h2 = __uint_as_float((unsigned)v2);
            float h3 = __uint_as_float((unsigned)v3);
            *(ulonglong2*)&hd[tid][0] = make_ulonglong2(pk2(h0, h0), pk2(h1, h1));
            *(ulonglong2*)&hd[tid][2] = make_ulonglong2(pk2(h2, h2), pk2(h3, h3));
        }
        __syncthreads();

        // ---- sub-GEMM: (4 batch) x (4 cols) over k in [32ks, 32ks+32) ----
        ull a00, a01, a10, a11, a20, a21, a30, a31;
        a00 = a01 = a10 = a11 = a20 = a21 = a30 = a31 = pk2(0.f, 0.f);
        {
            const ull* hp = &hd[ks * 32][0];
#pragma unroll
            for (int kk = 0; kk < 32; kk++) {
                ulonglong2 d0 = *(const ulonglong2*)(hp + kk * 4);
                ulonglong2 d1 = *(const ulonglong2*)(hp + kk * 4 + 2);
                a00 = ffma2(d0.x, wA[kk], a00); a01 = ffma2(d0.x, wB[kk], a01);
                a10 = ffma2(d0.y, wA[kk], a10); a11 = ffma2(d0.y, wB[kk], a11);
                a20 = ffma2(d1.x, wA[kk], a20); a21 = ffma2(d1.x, wB[kk], a21);
                a30 = ffma2(d1.y, wA[kk], a30); a31 = ffma2(d1.y, wB[kk], a31);
            }
        }
        {   // stage partials: red_s[b][tid] — coalesced, conflict-free
            float4 v;
            upk2(a00, v.x, v.y); upk2(a01, v.z, v.w); red_s[0][tid] = v;
            upk2(a10, v.x, v.y); upk2(a11, v.z, v.w); red_s[1][tid] = v;
            upk2(a20, v.x, v.y); upk2(a21, v.z, v.w); red_s[2][tid] = v;
            upk2(a30, v.x, v.y); upk2(a31, v.z, v.w); red_s[3][tid] = v;
        }
        __syncthreads();

        // ---- reduce 8 K-splits + x_proj -> gates ----
        if (tid < 128) {
            float4 s = xp4;
#pragma unroll
            for (int j = 0; j < 8; j++) {
                float4 v = red_s[rb][j * 32 + rc];
                s.x += v.x; s.y += v.y; s.z += v.z; s.w += v.w;
            }
            *(float4*)&gates_s[rb][4 * rc] = s;
        }
        __syncthreads();

        // ---- activations + state update + tagged publish ----
        if (tid < 128) {
            float gi = gates_s[rb][      rc];
            float gf = gates_s[rb][ 32 + rc];
            float gg = gates_s[rb][ 64 + rc];
            float go = gates_s[rb][ 96 + rc];
            float i_ = fsig(gi), f_ = fsig(gf), g_ = ftanh(gg), o_ = fsig(go);
            cstate = f_ * cstate + i_ * g_;
            float h_ = o_ * ftanh(cstate);
            hlast = h_;
            const int kidx = 32 * r + rc;
            // publish FIRST (latency-critical), then archive to out
            ull pv = (ull)__float_as_uint(h_) | ((ull)(unsigned)(t + 1) << 32);
            st_rlx(ht + ((size_t)((t + 1) & 1) * HID + kidx) * BG + rb, pv);
            out[((size_t)(batch0 + rb) * SEQ + t) * HID + kidx] = h_;
        }

        // ---- prefetch next step's x_proj (hidden under peers' polls) ----
        if (tid < 128) {
            int tn = (t + 1 < SEQ) ? (t + 1) : t;
            xp4 = *(const float4*)&xp_buf[xbase + (size_t)tn * G4];
        }
        // no barrier: the top-of-loop poll is the synchronization
    }

    // ---- h_n (second output region) ----
    if (tid < 128 && out_size >= (long long)BATCH * SEQ * HID + BATCH * HID) {
        out[(size_t)BATCH * SEQ * HID + (size_t)(batch0 + rb) * HID + 32 * r + rc] = hlast;
    }
}

// ============================================================
extern "C" void kernel_launch(void* const* d_in, const int* in_sizes, int n_in,
                              void* d_out, int out_size)
{
    const float* x  = (const float*)d_in[0];
    const float* WX = (const float*)d_in[1];
    const float* WH = (const float*)d_in[2];
    const float* BX = (const float*)d_in[3];
    const float* BH = (const float*)d_in[4];
    float* out = (float*)d_out;

    init_kernel<<<64, 256>>>();

    dim3 gx((BATCH * SEQ) / 64, G4 / 64);
    xproj_kernel<<<gx, 256>>>(x, WX, BX, BH);

    lstm_kernel<<<NGROUP * NCTA_PG, 256>>>(out, WH, (long long)out_size);
}

// round 5
// speedup vs baseline: 3.2437x; 1.1932x over previous
#include <cuda_runtime.h>
#include <stdint.h>

typedef unsigned long long ull;

// ---------- f32x2 packed-fp32 helpers ----------
__device__ __forceinline__ ull pk2(float lo, float hi) {
    ull r; asm("mov.b64 %0,{%1,%2};" : "=l"(r) : "f"(lo), "f"(hi)); return r;
}
__device__ __forceinline__ void upk2(ull v, float& lo, float& hi) {
    asm("mov.b64 {%0,%1},%2;" : "=f"(lo), "=f"(hi) : "l"(v));
}
__device__ __forceinline__ ull ffma2(ull a, ull b, ull c) {
    ull d; asm("fma.rn.f32x2 %0,%1,%2,%3;" : "=l"(d) : "l"(a), "l"(b), "l"(c)); return d;
}

// ---------- relaxed 64-bit L2 atoms (tag+data in one word) ----------
__device__ __forceinline__ ull ld_rlx(const ull* p) {
    ull v;
    asm volatile("ld.relaxed.gpu.global.u64 %0, [%1];" : "=l"(v) : "l"(p) : "memory");
    return v;
}
__device__ __forceinline__ void st_rlx(ull* p, ull v) {
    asm volatile("st.relaxed.gpu.global.u64 [%0], %1;" :: "l"(p), "l"(v) : "memory");
}

// ---------- problem constants ----------
#define BATCH   64
#define SEQ     2048
#define FEAT    256
#define HID     256
#define G4      1024           // 4*HID
#define BG      4              // batches per group
#define NCTA_PG 8              // CTAs per group
#define NGROUP  16

// ---------- scratch ----------
__device__ ull ht_buf[NGROUP * 2 * HID * BG];   // tagged h: lo=h bits, hi=step tag

// ============================================================
__global__ void init_kernel() {
    int t = blockIdx.x * blockDim.x + threadIdx.x;
    if (t < NGROUP * HID * BG) {
        int grp = t / (HID * BG);
        int rem = t % (HID * BG);
        ht_buf[(size_t)grp * 2 * HID * BG + rem] = 0ull;   // parity-0 slots: tag 0, h=0
    }
}

// ============================================================
// Fused LSTM: 16 groups x 8 CTAs. gates(t) = [x(t),h(t)] @ [WX;WH].
// WH slice in 128 REGISTERS/thread; WX slice pre-packed in SMEM (128KB).
// Pipeline: xp-partials(t) computed LAST iteration fill the window
// where peers' tagged h publishes are in flight in L2.
// ============================================================
__device__ __forceinline__ float fsig(float x) {
    return __fdividef(1.0f, 1.0f + __expf(-x));
}
__device__ __forceinline__ float ftanh(float x) { return 2.0f * fsig(2.0f * x) - 1.0f; }

__global__ __launch_bounds__(256, 1)
void lstm_kernel(float* __restrict__ out,
                 const float* __restrict__ x,
                 const float* __restrict__ WX,
                 const float* __restrict__ WH,
                 const float* __restrict__ BX,
                 const float* __restrict__ BH,
                 long long out_size)
{
    extern __shared__ char smem[];
    ulonglong2* wx_s    = (ulonglong2*)smem;                    // [256][32] (wA,wB)  128 KB
    ull*        hd      = (ull*)(smem + 131072);                // [256][4] (h,h)      8 KB
    ull*        xd      = (ull*)(smem + 131072 + 8192);         // [2][256][4] (x,x)  16 KB
    float4*     red_s   = (float4*)(smem + 131072 + 8192 + 16384);  // [4][256]       16 KB
    float*      gates_s = (float*)(smem + 131072 + 8192 + 16384 + 16384); // [4][128]  2 KB

    const int tid = threadIdx.x;
    const int grp = blockIdx.x >> 3;
    const int r   = blockIdx.x & 7;
    const int batch0 = grp * BG;

    const int ks = tid >> 5;            // K-split warp 0..7
    const int cq = tid & 31;            // col-quad (local cols 4cq..4cq+3)
    const int rb = tid >> 5;            // act batch (tid<128)
    const int rc = tid & 31;            // act hidden unit / reducer col-quad

    // ---- load WX slice into SMEM, pre-packed (wA,wB) ----
    for (int idx = tid; idx < 256 * 32; idx += 256) {
        int f = idx >> 5, ci = idx & 31;
        int gc = (ci >> 3) * HID + 32 * r + ((4 * ci) & 31);
        float4 w4 = *(const float4*)&WX[(size_t)f * G4 + gc];
        wx_s[idx] = make_ulonglong2(pk2(w4.x, w4.y), pk2(w4.z, w4.w));
    }

    // ---- load WH slice into registers (f32x2-packed col pairs) ----
    ull wA[32], wB[32];
    {
        const int gc = (cq >> 3) * HID + 32 * r + ((4 * cq) & 31);
        const float* wp = WH + (size_t)(32 * ks) * G4 + gc;
#pragma unroll
        for (int kk = 0; kk < 32; kk++) {
            float4 w4 = *(const float4*)(wp + (size_t)kk * G4);
            wA[kk] = pk2(w4.x, w4.y);
            wB[kk] = pk2(w4.z, w4.w);
        }
    }

    // ---- bias (folded once): per (rb,rc) thread, 4 gate cols ----
    float4 bias4 = make_float4(0.f, 0.f, 0.f, 0.f);
    if (tid < 128) {
        int gc = (rc >> 3) * HID + 32 * r + ((4 * rc) & 31);
        float4 bx4 = *(const float4*)&BX[gc];
        float4 bh4 = *(const float4*)&BH[gc];
        bias4 = make_float4(bx4.x + bh4.x, bx4.y + bh4.y, bx4.z + bh4.z, bx4.w + bh4.w);
    }

    // ---- x prefetch: thread owns feat=tid, 4 batches ----
    const float* xp0 = x + (size_t)batch0 * SEQ * FEAT + tid;
    float xr0, xr1, xr2, xr3;
    // x(0) -> xd[0] directly
    {
        float a0 = xp0[0 * (size_t)SEQ * FEAT];
        float a1 = xp0[1 * (size_t)SEQ * FEAT];
        float a2 = xp0[2 * (size_t)SEQ * FEAT];
        float a3 = xp0[3 * (size_t)SEQ * FEAT];
        ull* xw = xd + (size_t)tid * BG;                    // parity 0
        *(ulonglong2*)(xw + 0) = make_ulonglong2(pk2(a0, a0), pk2(a1, a1));
        *(ulonglong2*)(xw + 2) = make_ulonglong2(pk2(a2, a2), pk2(a3, a3));
    }
    // x(1) -> regs
    xr0 = xp0[(size_t)1 * FEAT + 0 * (size_t)SEQ * FEAT];
    xr1 = xp0[(size_t)1 * FEAT + 1 * (size_t)SEQ * FEAT];
    xr2 = xp0[(size_t)1 * FEAT + 2 * (size_t)SEQ * FEAT];
    xr3 = xp0[(size_t)1 * FEAT + 3 * (size_t)SEQ * FEAT];

    __syncthreads();   // wx_s + xd[0] visible

    ull* ht = &ht_buf[(size_t)grp * 2 * HID * BG];   // [parity][k][b]

    // ---- accumulators: xp-partials(t) live here between iterations ----
    ull a00, a01, a10, a11, a20, a21, a30, a31;

    // ---- prologue: xp-GEMM(0) ----
    a00 = a01 = a10 = a11 = a20 = a21 = a30 = a31 = pk2(0.f, 0.f);
    {
        const ull* xp_ = xd + (size_t)(ks * 32) * BG;       // parity 0
        const ulonglong2* wp = wx_s + (size_t)(ks * 32) * 32 + cq;
#pragma unroll
        for (int kk = 0; kk < 32; kk++) {
            ulonglong2 d0 = *(const ulonglong2*)(xp_ + kk * 4);
            ulonglong2 d1 = *(const ulonglong2*)(xp_ + kk * 4 + 2);
            ulonglong2 w2 = wp[kk * 32];
            a00 = ffma2(d0.x, w2.x, a00); a01 = ffma2(d0.x, w2.y, a01);
            a10 = ffma2(d0.y, w2.x, a10); a11 = ffma2(d0.y, w2.y, a11);
            a20 = ffma2(d1.x, w2.x, a20); a21 = ffma2(d1.x, w2.y, a21);
            a30 = ffma2(d1.y, w2.x, a30); a31 = ffma2(d1.y, w2.y, a31);
        }
    }

    float cstate = 0.0f, hlast = 0.0f;

    for (int t = 0; t < SEQ; t++) {
        // ---- top: stage x(t+1) -> xd[(t+1)&1]; poll tagged h(t) ----
        {
            ull* xw = xd + ((size_t)((t + 1) & 1) * HID + tid) * BG;
            *(ulonglong2*)(xw + 0) = make_ulonglong2(pk2(xr0, xr0), pk2(xr1, xr1));
            *(ulonglong2*)(xw + 2) = make_ulonglong2(pk2(xr2, xr2), pk2(xr3, xr3));
        }
        {
            ull* sp = ht + ((size_t)(t & 1) * HID + tid) * BG;
            const unsigned tg = (unsigned)t;
            ull v0 = ld_rlx(sp + 0), v1 = ld_rlx(sp + 1);
            ull v2 = ld_rlx(sp + 2), v3 = ld_rlx(sp + 3);
            while (((unsigned)(v0 >> 32) != tg) | ((unsigned)(v1 >> 32) != tg) |
                   ((unsigned)(v2 >> 32) != tg) | ((unsigned)(v3 >> 32) != tg)) {
                v0 = ld_rlx(sp + 0); v1 = ld_rlx(sp + 1);
                v2 = ld_rlx(sp + 2); v3 = ld_rlx(sp + 3);
            }
            float h0 = __uint_as_float((unsigned)v0);
            float h1 = __uint_as_float((unsigned)v1);
            float h2 = __uint_as_float((unsigned)v2);
            float h3 = __uint_as_float((unsigned)v3);
            ull* hw = hd + (size_t)tid * BG;
            *(ulonglong2*)(hw + 0) = make_ulonglong2(pk2(h0, h0), pk2(h1, h1));
            *(ulonglong2*)(hw + 2) = make_ulonglong2(pk2(h2, h2), pk2(h3, h3));
        }
        __syncthreads();

        // ---- h-GEMM: accumulate onto xp-partials(t) already in acc ----
        {
            const ull* hp = hd + (size_t)(ks * 32) * BG;
#pragma unroll
            for (int kk = 0; kk < 32; kk++) {
                ulonglong2 d0 = *(const ulonglong2*)(hp + kk * 4);
                ulonglong2 d1 = *(const ulonglong2*)(hp + kk * 4 + 2);
                a00 = ffma2(d0.x, wA[kk], a00); a01 = ffma2(d0.x, wB[kk], a01);
                a10 = ffma2(d0.y, wA[kk], a10); a11 = ffma2(d0.y, wB[kk], a11);
                a20 = ffma2(d1.x, wA[kk], a20); a21 = ffma2(d1.x, wB[kk], a21);
                a30 = ffma2(d1.y, wA[kk], a30); a31 = ffma2(d1.y, wB[kk], a31);
            }
        }
        {   // stage partials
            float4 v;
            upk2(a00, v.x, v.y); upk2(a01, v.z, v.w); red_s[0 * 256 + tid] = v;
            upk2(a10, v.x, v.y); upk2(a11, v.z, v.w); red_s[1 * 256 + tid] = v;
            upk2(a20, v.x, v.y); upk2(a21, v.z, v.w); red_s[2 * 256 + tid] = v;
            upk2(a30, v.x, v.y); upk2(a31, v.z, v.w); red_s[3 * 256 + tid] = v;
        }
        __syncthreads();

        // ---- reduce(+bias) -> gates ----
        if (tid < 128) {
            float4 s = bias4;
#pragma unroll
            for (int j = 0; j < 8; j++) {
                float4 v = red_s[rb * 256 + j * 32 + rc];
                s.x += v.x; s.y += v.y; s.z += v.z; s.w += v.w;
            }
            *(float4*)&gates_s[rb * 128 + 4 * rc] = s;
        }
        __syncwarp();
        if (tid < 128) {
            float gi = gates_s[rb * 128 +       rc];
            float gf = gates_s[rb * 128 +  32 + rc];
            float gg = gates_s[rb * 128 +  64 + rc];
            float go = gates_s[rb * 128 +  96 + rc];
            float i_ = fsig(gi), f_ = fsig(gf), g_ = ftanh(gg), o_ = fsig(go);
            cstate = f_ * cstate + i_ * g_;
            float h_ = o_ * ftanh(cstate);
            hlast = h_;
            const int kidx = 32 * r + rc;
            ull pv = (ull)__float_as_uint(h_) | ((ull)(unsigned)(t + 1) << 32);
            st_rlx(ht + ((size_t)((t + 1) & 1) * HID + kidx) * BG + rb, pv);
            out[((size_t)(batch0 + rb) * SEQ + t) * HID + kidx] = h_;
        }

        // ---- prefetch x(t+2) ----
        {
            size_t tn = (size_t)((t + 2 < SEQ) ? (t + 2) : t) * FEAT;
            xr0 = xp0[tn + 0 * (size_t)SEQ * FEAT];
            xr1 = xp0[tn + 1 * (size_t)SEQ * FEAT];
            xr2 = xp0[tn + 2 * (size_t)SEQ * FEAT];
            xr3 = xp0[tn + 3 * (size_t)SEQ * FEAT];
        }

        // ---- xp-GEMM(t+1): fills the publish->poll latency window ----
        a00 = a01 = a10 = a11 = a20 = a21 = a30 = a31 = pk2(0.f, 0.f);
        {
            const ull* xp_ = xd + ((size_t)((t + 1) & 1) * HID + ks * 32) * BG;
            const ulonglong2* wp = wx_s + (size_t)(ks * 32) * 32 + cq;
#pragma unroll
            for (int kk = 0; kk < 32; kk++) {
                ulonglong2 d0 = *(const ulonglong2*)(xp_ + kk * 4);
                ulonglong2 d1 = *(const ulonglong2*)(xp_ + kk * 4 + 2);
                ulonglong2 w2 = wp[kk * 32];
                a00 = ffma2(d0.x, w2.x, a00); a01 = ffma2(d0.x, w2.y, a01);
                a10 = ffma2(d0.y, w2.x, a10); a11 = ffma2(d0.y, w2.y, a11);
                a20 = ffma2(d1.x, w2.x, a20); a21 = ffma2(d1.x, w2.y, a21);
                a30 = ffma2(d1.y, w2.x, a30); a31 = ffma2(d1.y, w2.y, a31);
            }
        }
        // no trailing barrier: top-of-loop poll + syncthreads covers ordering
    }

    // ---- h_n (second output region) ----
    if (tid < 128 && out_size >= (long long)BATCH * SEQ * HID + BATCH * HID) {
        out[(size_t)BATCH * SEQ * HID + (size_t)(batch0 + rb) * HID + 32 * r + rc] = hlast;
    }
}

// ============================================================
extern "C" void kernel_launch(void* const* d_in, const int* in_sizes, int n_in,
                              void* d_out, int out_size)
{
    const float* x  = (const float*)d_in[0];
    const float* WX = (const float*)d_in[1];
    const float* WH = (const float*)d_in[2];
    const float* BX = (const float*)d_in[3];
    const float* BH = (const float*)d_in[4];
    float* out = (float*)d_out;

    const size_t smem_bytes = 131072 + 8192 + 16384 + 16384 + 2048;  // 174080
    static int configured = -1;
    cudaFuncSetAttribute(lstm_kernel, cudaFuncAttributeMaxDynamicSharedMemorySize,
                         (int)smem_bytes);
    (void)configured;

    init_kernel<<<64, 256>>>();
    lstm_kernel<<<NGROUP * NCTA_PG, 256, smem_bytes>>>(
        out, x, WX, WH, BX, BH, (long long)out_size);
}